// round 16
// baseline (speedup 1.0000x reference)
#include <cuda_runtime.h>
#include <cstdint>

// PolarToCartesianGrid: batched scatter-add into a cartesian voxel grid.
//
// R16: serial schedule (pack -> engine memset -> scatter; reliable) with the
// radial-quad scatter PLUS a 2-batch unroll.
//   R15 diagnosis: quad scatter (fewer REDs: ~430K vs 784K/batch) was
//   latency-bound at 262K threads (issue 20%). Fix: process batch PAIRS —
//   8 polar loads in flight (MLP 8), 4 interleaved segmented-reduction
//   chains, 8 REDs per iteration. Structure (batch-invariant) packed once.

#define NTHR 256
#define MAX_QUADS (1 << 19)
#define M23 0x7FFFFFu
#define SENT 0x7FFFFFu          // sentinel idx (n_vox < 2^23)

__device__ uint4 g_packed4[MAX_QUADS];

//  w.x = i0 | fA<<23   (fA: bit0 head, bits1-5 same@d=1,2,4,8,16 on A-idx)
//  w.y = i1 | m1e<<23 | mjoin<<24 | sA1<<25 | sA2<<26 | sA3<<27
//  w.z = i2 | m2e<<23 | sB1<<24  | sB2<<25
//  w.w = i3 | fB<<23  | alive<<29
__global__ void pack_quad_kernel(const int* __restrict__ vidx, int n_quads)
{
    const int q = blockIdx.x * blockDim.x + threadIdx.x;
    if (q >= n_quads) return;                   // n_quads % 256 == 0
    const unsigned FULL = 0xFFFFFFFFu;
    const int lane = threadIdx.x & 31;

    const int az   = q & 127;                   // Az = 128
    const int base = ((q >> 7) << 9) + az;      // rowquad*512 + az

    const int i0 = vidx[base];
    const int i1 = vidx[base + 128];
    const int i2 = vidx[base + 256];
    const int i3 = vidx[base + 384];

    const bool e1 = (i1 == i0), e2 = (i2 == i1), e3 = (i3 == i2);
    const bool sA1 = e1, sA2 = e1 && e2, sA3 = e1 && e2 && e3;
    const bool alive = !sA3;                    // B slot exists
    const bool sB2 = e3, sB1 = e3 && e2;

    const bool covB1 = sB1 && alive, covB2 = sB2 && alive;
    const bool m1 = !sA1 && !covB1;             // cell1 interior
    const bool m2 = !sA2 && !covB2;             // cell2 interior
    const bool mjoin = m1 && m2 && e2;          // cells 1,2 one interior run
    const bool m1e = m1;
    const bool m2e = m2 && !mjoin;

    // A-slot az flags (segmented suffix reduction over i0 across lanes)
    const int pA = __shfl_up_sync(FULL, i0, 1);
    unsigned fA = (lane == 0 || pA != i0) ? 1u : 0u;
    int t;
    t = __shfl_down_sync(FULL, i0, 1);  if (lane + 1  < 32 && t == i0) fA |= 2u;
    t = __shfl_down_sync(FULL, i0, 2);  if (lane + 2  < 32 && t == i0) fA |= 4u;
    t = __shfl_down_sync(FULL, i0, 4);  if (lane + 4  < 32 && t == i0) fA |= 8u;
    t = __shfl_down_sync(FULL, i0, 8);  if (lane + 8  < 32 && t == i0) fA |= 16u;
    t = __shfl_down_sync(FULL, i0, 16); if (lane + 16 < 32 && t == i0) fA |= 32u;

    // B-slot az flags on sentineled idx (dead lanes break runs, never emit)
    const int bidx = alive ? i3 : (int)SENT;
    const int pB = __shfl_up_sync(FULL, bidx, 1);
    unsigned fB = (alive && (lane == 0 || pB != bidx)) ? 1u : 0u;
    t = __shfl_down_sync(FULL, bidx, 1);  if (lane + 1  < 32 && t == bidx) fB |= 2u;
    t = __shfl_down_sync(FULL, bidx, 2);  if (lane + 2  < 32 && t == bidx) fB |= 4u;
    t = __shfl_down_sync(FULL, bidx, 4);  if (lane + 4  < 32 && t == bidx) fB |= 8u;
    t = __shfl_down_sync(FULL, bidx, 8);  if (lane + 8  < 32 && t == bidx) fB |= 16u;
    t = __shfl_down_sync(FULL, bidx, 16); if (lane + 16 < 32 && t == bidx) fB |= 32u;

    uint4 w;
    w.x = (unsigned)i0 | (fA << 23);
    w.y = (unsigned)i1 | ((unsigned)m1e << 23) | ((unsigned)mjoin << 24)
        | ((unsigned)sA1 << 25) | ((unsigned)sA2 << 26) | ((unsigned)sA3 << 27);
    w.z = (unsigned)i2 | ((unsigned)m2e << 23)
        | ((unsigned)sB1 << 24) | ((unsigned)sB2 << 25);
    w.w = (unsigned)i3 | (fB << 23) | ((unsigned)alive << 29);
    g_packed4[q] = w;
}

__global__ __launch_bounds__(NTHR)
void scatter_quad2_kernel(const float* __restrict__ polar,
                          float*       __restrict__ out,
                          int n_cells, int batches, long long n_vox, int n_quads)
{
    const int q = blockIdx.x * blockDim.x + threadIdx.x;
    if (q >= n_quads) return;
    const unsigned FULL = 0xFFFFFFFFu;

    const int az   = q & 127;
    const int base = ((q >> 7) << 9) + az;

    const uint4 w = g_packed4[q];
    const unsigned i0 = w.x & M23, fA = (w.x >> 23) & 63u;
    const unsigned i1 = w.y & M23;
    const bool  m1e   = (w.y >> 23) & 1u;
    const float mj    = ((w.y >> 24) & 1u) ? 1.f : 0.f;
    const float mA1   = ((w.y >> 25) & 1u) ? 1.f : 0.f;
    const float mA2   = ((w.y >> 26) & 1u) ? 1.f : 0.f;
    const float mA3   = ((w.y >> 27) & 1u) ? 1.f : 0.f;
    const unsigned i2 = w.z & M23;
    const bool  m2e   = (w.z >> 23) & 1u;
    const float mB1   = ((w.z >> 24) & 1u) ? 1.f : 0.f;
    const float mB2   = ((w.z >> 25) & 1u) ? 1.f : 0.f;
    const unsigned i3 = w.w & M23, fB = (w.w >> 23) & 63u;
    const float mAl   = ((w.w >> 29) & 1u) ? 1.f : 0.f;

    int b = 0;
    for (; b + 1 < batches; b += 2) {
        // ---- 8 loads in flight across the batch pair (MLP 8) ----
        const float* p0 = polar + (size_t)b * n_cells + base;
        const float* p1 = p0 + n_cells;
        const float x0 = __ldg(p0);       const float y0 = __ldg(p1);
        const float x1 = __ldg(p0 + 128); const float y1 = __ldg(p1 + 128);
        const float x2 = __ldg(p0 + 256); const float y2 = __ldg(p1 + 256);
        const float x3 = __ldg(p0 + 384); const float y3 = __ldg(p1 + 384);

        float vA0 = x0 + mA1 * x1 + mA2 * x2 + mA3 * x3;
        float vB0 = mAl * (x3 + mB2 * x2 + mB1 * x1);
        const float mv0 = x1 + mj * x2;
        float vA1 = y0 + mA1 * y1 + mA2 * y2 + mA3 * y3;
        float vB1 = mAl * (y3 + mB2 * y2 + mB1 * y1);
        const float mv1 = y1 + mj * y2;

        // ---- 4 interleaved az-segmented suffix reductions ----
        float ta0, tb0, ta1, tb1;
        ta0 = __shfl_down_sync(FULL, vA0, 1);  tb0 = __shfl_down_sync(FULL, vB0, 1);
        ta1 = __shfl_down_sync(FULL, vA1, 1);  tb1 = __shfl_down_sync(FULL, vB1, 1);
        if (fA & 2u)  { vA0 += ta0; vA1 += ta1; }
        if (fB & 2u)  { vB0 += tb0; vB1 += tb1; }
        ta0 = __shfl_down_sync(FULL, vA0, 2);  tb0 = __shfl_down_sync(FULL, vB0, 2);
        ta1 = __shfl_down_sync(FULL, vA1, 2);  tb1 = __shfl_down_sync(FULL, vB1, 2);
        if (fA & 4u)  { vA0 += ta0; vA1 += ta1; }
        if (fB & 4u)  { vB0 += tb0; vB1 += tb1; }
        ta0 = __shfl_down_sync(FULL, vA0, 4);  tb0 = __shfl_down_sync(FULL, vB0, 4);
        ta1 = __shfl_down_sync(FULL, vA1, 4);  tb1 = __shfl_down_sync(FULL, vB1, 4);
        if (fA & 8u)  { vA0 += ta0; vA1 += ta1; }
        if (fB & 8u)  { vB0 += tb0; vB1 += tb1; }
        ta0 = __shfl_down_sync(FULL, vA0, 8);  tb0 = __shfl_down_sync(FULL, vB0, 8);
        ta1 = __shfl_down_sync(FULL, vA1, 8);  tb1 = __shfl_down_sync(FULL, vB1, 8);
        if (fA & 16u) { vA0 += ta0; vA1 += ta1; }
        if (fB & 16u) { vB0 += tb0; vB1 += tb1; }
        ta0 = __shfl_down_sync(FULL, vA0, 16); tb0 = __shfl_down_sync(FULL, vB0, 16);
        ta1 = __shfl_down_sync(FULL, vA1, 16); tb1 = __shfl_down_sync(FULL, vB1, 16);
        if (fA & 32u) { vA0 += ta0; vA1 += ta1; }
        if (fB & 32u) { vB0 += tb0; vB1 += tb1; }

        float* ob0 = out + (long long)b * n_vox;
        float* ob1 = ob0 + n_vox;
        if (fA & 1u) { atomicAdd(ob0 + i0, vA0); atomicAdd(ob1 + i0, vA1); }
        if (fB & 1u) { atomicAdd(ob0 + i3, vB0); atomicAdd(ob1 + i3, vB1); }
        if (m1e)     { atomicAdd(ob0 + i1, mv0); atomicAdd(ob1 + i1, mv1); }
        if (m2e)     { atomicAdd(ob0 + i2, x2);  atomicAdd(ob1 + i2, y2);  }
    }

    // odd tail batch (not hit for batches=16)
    for (; b < batches; ++b) {
        const float* p0 = polar + (size_t)b * n_cells + base;
        const float x0 = __ldg(p0);
        const float x1 = __ldg(p0 + 128);
        const float x2 = __ldg(p0 + 256);
        const float x3 = __ldg(p0 + 384);
        float vA0 = x0 + mA1 * x1 + mA2 * x2 + mA3 * x3;
        float vB0 = mAl * (x3 + mB2 * x2 + mB1 * x1);
        const float mv0 = x1 + mj * x2;
        float ta0, tb0;
        ta0 = __shfl_down_sync(FULL, vA0, 1);  tb0 = __shfl_down_sync(FULL, vB0, 1);
        if (fA & 2u)  vA0 += ta0;  if (fB & 2u)  vB0 += tb0;
        ta0 = __shfl_down_sync(FULL, vA0, 2);  tb0 = __shfl_down_sync(FULL, vB0, 2);
        if (fA & 4u)  vA0 += ta0;  if (fB & 4u)  vB0 += tb0;
        ta0 = __shfl_down_sync(FULL, vA0, 4);  tb0 = __shfl_down_sync(FULL, vB0, 4);
        if (fA & 8u)  vA0 += ta0;  if (fB & 8u)  vB0 += tb0;
        ta0 = __shfl_down_sync(FULL, vA0, 8);  tb0 = __shfl_down_sync(FULL, vB0, 8);
        if (fA & 16u) vA0 += ta0;  if (fB & 16u) vB0 += tb0;
        ta0 = __shfl_down_sync(FULL, vA0, 16); tb0 = __shfl_down_sync(FULL, vB0, 16);
        if (fA & 32u) vA0 += ta0;  if (fB & 32u) vB0 += tb0;
        float* ob0 = out + (long long)b * n_vox;
        if (fA & 1u) atomicAdd(ob0 + i0, vA0);
        if (fB & 1u) atomicAdd(ob0 + i3, vB0);
        if (m1e)     atomicAdd(ob0 + i1, mv0);
        if (m2e)     atomicAdd(ob0 + i2, x2);
    }
}

// fallback: R1-style serial scatter (no layout assumptions)
__global__ void scatter_fallback_kernel(const float* __restrict__ polar_b,
                                        const int*   __restrict__ vidx,
                                        float*       __restrict__ out_b,
                                        int n_cells)
{
    const int cell = blockIdx.x * blockDim.x + threadIdx.x;
    if (cell >= n_cells) return;
    const unsigned FULL = 0xFFFFFFFFu;
    const int lane = threadIdx.x & 31;
    const int idx = vidx[cell];
    float v = __ldg(polar_b + cell);
    const unsigned peers = __match_any_sync(FULL, idx);
    const int rank = __popc(peers & ((1u << lane) - 1u));
    const unsigned s1  = __fns(peers, lane, 2);
    const unsigned s2  = __fns(peers, lane, 3);
    const unsigned s4  = __fns(peers, lane, 5);
    const unsigned s8  = __fns(peers, lane, 9);
    const unsigned s16 = __fns(peers, lane, 17);
    float t;
    t = __shfl_sync(FULL, v, s1  & 31); if (s1  < 32) v += t;
    t = __shfl_sync(FULL, v, s2  & 31); if (s2  < 32) v += t;
    t = __shfl_sync(FULL, v, s4  & 31); if (s4  < 32) v += t;
    t = __shfl_sync(FULL, v, s8  & 31); if (s8  < 32) v += t;
    t = __shfl_sync(FULL, v, s16 & 31); if (s16 < 32) v += t;
    if (rank == 0) atomicAdd(out_b + idx, v);
}

extern "C" void kernel_launch(void* const* d_in, const int* in_sizes, int n_in,
                              void* d_out, int out_size)
{
    const float* polar = (const float*)d_in[0];            // [B,1,32,256,128] f32
    const int*   vidx  = (const int*)d_in[1];              // [1048576] int32
    float*       out   = (float*)d_out;                    // [B,1,80,320,320] f32

    const int n_cells = in_sizes[1];
    const int batches = in_sizes[0] / n_cells;             // 16
    const long long n_vox = (long long)out_size / batches; // 8,192,000

    // quad layout assumes El*R*Az with Az=128, R%4==0 (fixed for this problem)
    const bool quadable = (n_cells == (1 << 20)) && (n_vox < (1LL << 23));

    if (quadable) {
        const int n_quads = n_cells / 4;                   // 262144
        const int qblocks = n_quads / NTHR;                // 1024

        pack_quad_kernel<<<qblocks, NTHR>>>(vidx, n_quads);
        cudaMemsetAsync(d_out, 0, (size_t)out_size * sizeof(float), 0);
        scatter_quad2_kernel<<<qblocks, NTHR>>>(polar, out,
                                                n_cells, batches, n_vox, n_quads);
    } else {
        cudaMemsetAsync(d_out, 0, (size_t)out_size * sizeof(float), 0);
        const int blocks = (n_cells + NTHR - 1) / NTHR;
        for (int b = 0; b < batches; ++b)
            scatter_fallback_kernel<<<blocks, NTHR>>>(
                polar + (size_t)b * n_cells, vidx,
                out + (long long)b * n_vox, n_cells);
    }
}